// round 7
// baseline (speedup 1.0000x reference)
#include <cuda_runtime.h>

#define NGRAPH 256
#define M      512
#define KNN    6
#define C      32
#define NWARP  16          // 512 threads in main kernel
#define FINF   3.402823466e38f

typedef unsigned long long ull;

// inter-phase 'a' scratch + knn index scratch (L2-resident). Allocation-free.
__device__ float g_A[NGRAPH * M * C];
__device__ int   g_idx[NGRAPH * M * 8];

struct __align__(16) SmemLayout {
    float U[M * C];          // 64KB
    int   idxb[M * 8];       // 16KB byte-scaled neighbor offsets (idx*128), 6 used
    float hb[NWARP][2][C];   //  4KB per-warp h staging
    float red[NWARP * C];    //  2KB
};                           // ~86KB -> 2 CTAs/SM

static __device__ __forceinline__ ull pk2(float lo, float hi) {
    ull d; asm("mov.b64 %0, {%1, %2};" : "=l"(d) : "f"(lo), "f"(hi)); return d;
}
static __device__ __forceinline__ float2 upk2(ull v) {
    float2 r; asm("mov.b64 {%0, %1}, %2;" : "=f"(r.x), "=f"(r.y) : "l"(v)); return r;
}
static __device__ __forceinline__ ull ffma2(ull a, ull b, ull c) {
    ull d; asm("fma.rn.f32x2 %0, %1, %2, %3;" : "=l"(d) : "l"(a), "l"(b), "l"(c)); return d;
}

__device__ __forceinline__ void kins(float (&bd)[KNN], int (&bi)[KNN],
                                     float xd, int xi)
{
#pragma unroll
    for (int k = 0; k < KNN; k++) {
        bool  p  = xd < bd[k];          // strict: stable (ties keep earlier j)
        float td = bd[k];
        int   ti = bi[k];
        bd[k] = p ? xd : bd[k];
        bi[k] = p ? xi : bi[k];
        xd    = p ? td : xd;
        xi    = p ? ti : xi;
    }
}

// ============================================================================
// Kernel 1: brute-force KNN at high occupancy.
// 2 blocks per graph, 256 threads each; thread owns one node row.
// ============================================================================
__global__ void __launch_bounds__(256) knn_kernel(const float* __restrict__ pos)
{
    __shared__ float4 pos4s[M];       // 8KB
    const int b    = blockIdx.x >> 1;
    const int half = blockIdx.x & 1;
    const int tid  = threadIdx.x;

    // stage all 512 pos (+ |p|^2)
#pragma unroll
    for (int i = 0; i < 2; i++) {
        int n = i * 256 + tid;
        const float* p = pos + ((size_t)b * M + n) * 3;
        float px = p[0], py = p[1], pz = p[2];
        pos4s[n] = make_float4(px, py, pz, px * px + py * py + pz * pz);
    }
    __syncthreads();

    const int n = half * 256 + tid;
    float4 pn = pos4s[n];
    float bd[KNN];
    int   bi[KNN];
#pragma unroll
    for (int k = 0; k < KNN; k++) { bd[k] = FINF; bi[k] = 0; }
#pragma unroll 2
    for (int j = 0; j < M; j += 2) {
        float4 pa = pos4s[j];
        float4 pb = pos4s[j + 1];
        float dota = fmaf(pn.x, pa.x, fmaf(pn.y, pa.y, pn.z * pa.z));
        float dotb = fmaf(pn.x, pb.x, fmaf(pn.y, pb.y, pn.z * pb.z));
        float d2a  = fmaf(-2.0f, dota, pn.w + pa.w);
        float d2b  = fmaf(-2.0f, dotb, pn.w + pb.w);
        if (d2a < bd[KNN - 1]) kins(bd, bi, d2a, j);
        if (d2b < bd[KNN - 1]) kins(bd, bi, d2b, j + 1);
    }
    int* dst = g_idx + (size_t)b * M * 8 + n * 8;
    int4 v0 = make_int4(bi[0] << 7, bi[1] << 7, bi[2] << 7, bi[3] << 7);
    int4 v1 = make_int4(bi[4] << 7, bi[5] << 7, 0, 0);
    *(int4*)(dst)     = v0;
    *(int4*)(dst + 4) = v1;
}

// ============================================================================
// Kernel 2: fused 3-layer GCN + pool + head. One CTA per graph.
// ============================================================================
__global__ void __launch_bounds__(512, 2) gcn_layers_kernel(
    const float* __restrict__ x,   const float* __restrict__ pos,
    const float* __restrict__ W1a, const float* __restrict__ b1a,
    const float* __restrict__ W2a, const float* __restrict__ b2a,
    const float* __restrict__ W1b, const float* __restrict__ b1b,
    const float* __restrict__ W2b, const float* __restrict__ b2b,
    const float* __restrict__ W1c, const float* __restrict__ b1c,
    const float* __restrict__ W2c, const float* __restrict__ b2c,
    const float* __restrict__ Wr,  const float* __restrict__ brr,
    float* __restrict__ out)
{
    extern __shared__ char smem_raw[];
    SmemLayout& sm = *reinterpret_cast<SmemLayout*>(smem_raw);

    const int b    = blockIdx.x;
    const int tid  = threadIdx.x;
    const int lane = tid & 31;
    const int wid  = tid >> 5;
    const int base = wid * 32;

    float* __restrict__ Ag = g_A + (size_t)b * M * C;

    // ---- stage knn byte-offsets ----
    {
        const int4* src = (const int4*)(g_idx + (size_t)b * M * 8);
        int4* dst = (int4*)sm.idxb;
        dst[tid]       = src[tid];
        dst[tid + 512] = src[tid + 512];
    }

    float* hb0 = &sm.hb[wid][0][0];
    float* hb1 = &sm.hb[wid][1][0];

    // ---------- ph2 (all layers): u = W2·A(own rows) + b2 -> U (in place)
    auto ph2 = [&](const float* __restrict__ W2, const float* __restrict__ B2) {
        ull wp[16];
#pragma unroll
        for (int t = 0; t < 16; t++) {
            float2 wv = ((const float2*)W2)[lane * 16 + t];
            wp[t] = pk2(wv.x, wv.y);
        }
        float bb = B2[lane];
#pragma unroll 1
        for (int t = 0; t < 16; t++) {
            int n0 = base + 2 * t, n1 = n0 + 1;
            const ulonglong2* r0 = (const ulonglong2*)(Ag + n0 * C);
            const ulonglong2* r1 = (const ulonglong2*)(Ag + n1 * C);
            ull a00 = 0, a01 = 0, a10 = 0, a11 = 0;
#pragma unroll
            for (int q = 0; q < 8; q++) {
                ulonglong2 v0 = r0[q], v1 = r1[q];
                a00 = ffma2(wp[2*q], v0.x, a00); a01 = ffma2(wp[2*q+1], v0.y, a01);
                a10 = ffma2(wp[2*q], v1.x, a10); a11 = ffma2(wp[2*q+1], v1.y, a11);
            }
            float2 e0 = upk2(a00), e1 = upk2(a01);
            float2 e2 = upk2(a10), e3 = upk2(a11);
            sm.U[n0 * C + lane] = bb + ((e0.x + e0.y) + (e1.x + e1.y));
            sm.U[n1 * C + lane] = bb + ((e2.x + e2.y) + (e3.x + e3.y));
        }
    };

    // ========= layer A ph1: a = relu(W1a·[x,pos]+b1a) -> Ag (global pos reads) ====
    {
        float w10 = W1a[lane * 4 + 0], w11 = W1a[lane * 4 + 1];
        float w12 = W1a[lane * 4 + 2], w13 = W1a[lane * 4 + 3];
        float bb1 = b1a[lane];
        const float* pb = pos + (size_t)b * M * 3;
        const float* xb = x + (size_t)b * M;
#pragma unroll 1
        for (int t = 0; t < 16; t++) {
            int n0 = base + 2 * t, n1 = n0 + 1;
            float p0x = pb[n0*3], p0y = pb[n0*3+1], p0z = pb[n0*3+2];
            float p1x = pb[n1*3], p1y = pb[n1*3+1], p1z = pb[n1*3+2];
            float x0 = xb[n0], x1 = xb[n1];
            float a0 = fmaf(w10, x0, fmaf(w11, p0x, fmaf(w12, p0y, fmaf(w13, p0z, bb1))));
            float a1 = fmaf(w10, x1, fmaf(w11, p1x, fmaf(w12, p1y, fmaf(w13, p1z, bb1))));
            Ag[n0 * C + lane] = fmaxf(a0, 0.0f);
            Ag[n1 * C + lane] = fmaxf(a1, 0.0f);
        }
    }
    // no barrier: ph2 reads only own-warp Ag rows
    ph2(W2a, b2a);
    __syncthreads();   // U complete + idxb staged before gathers

    // ===================== layers B, C =====================
    auto ph1_32 = [&](const float* __restrict__ W1, const float* __restrict__ B1) {
        ull wp[16];
#pragma unroll
        for (int t = 0; t < 16; t++) {
            float2 wv = ((const float2*)W1)[lane * 16 + t];
            wp[t] = pk2(wv.x, wv.y);
        }
        float bb = B1[lane];
        const char* Ub = (const char*)sm.U + lane * 4;
#pragma unroll 1
        for (int t = 0; t < 16; t++) {
            int n0 = base + 2 * t, n1 = n0 + 1;
            const int4 ia0 = *(const int4*)&sm.idxb[n0 * 8];
            const int2 ib0 = *(const int2*)&sm.idxb[n0 * 8 + 4];
            const int4 ia1 = *(const int4*)&sm.idxb[n1 * 8];
            const int2 ib1 = *(const int2*)&sm.idxb[n1 * 8 + 4];
            float m0 =            *(const float*)(Ub + ia0.x);
            m0 = fmaxf(m0, *(const float*)(Ub + ia0.y));
            m0 = fmaxf(m0, *(const float*)(Ub + ia0.z));
            m0 = fmaxf(m0, *(const float*)(Ub + ia0.w));
            m0 = fmaxf(m0, *(const float*)(Ub + ib0.x));
            m0 = fmaxf(m0, *(const float*)(Ub + ib0.y));
            float m1 =            *(const float*)(Ub + ia1.x);
            m1 = fmaxf(m1, *(const float*)(Ub + ia1.y));
            m1 = fmaxf(m1, *(const float*)(Ub + ia1.z));
            m1 = fmaxf(m1, *(const float*)(Ub + ia1.w));
            m1 = fmaxf(m1, *(const float*)(Ub + ib1.x));
            m1 = fmaxf(m1, *(const float*)(Ub + ib1.y));
            hb0[lane] = fmaxf(m0, 0.0f);
            hb1[lane] = fmaxf(m1, 0.0f);
            __syncwarp();
            const ulonglong2* h0 = (const ulonglong2*)hb0;
            const ulonglong2* h1 = (const ulonglong2*)hb1;
            ull a00 = 0, a01 = 0, a10 = 0, a11 = 0;
#pragma unroll
            for (int q = 0; q < 8; q++) {
                ulonglong2 v0 = h0[q], v1 = h1[q];
                a00 = ffma2(wp[2*q], v0.x, a00); a01 = ffma2(wp[2*q+1], v0.y, a01);
                a10 = ffma2(wp[2*q], v1.x, a10); a11 = ffma2(wp[2*q+1], v1.y, a11);
            }
            float2 e0 = upk2(a00), e1 = upk2(a01);
            float2 e2 = upk2(a10), e3 = upk2(a11);
            Ag[n0 * C + lane] = fmaxf(bb + ((e0.x + e0.y) + (e1.x + e1.y)), 0.0f);
            Ag[n1 * C + lane] = fmaxf(bb + ((e2.x + e2.y) + (e3.x + e3.y)), 0.0f);
            __syncwarp();
        }
    };

    ph1_32(W1b, b1b);
    __syncthreads();   // all gathers from U done before ph2 overwrites U
    ph2(W2b, b2b);
    __syncthreads();

    ph1_32(W1c, b1c);
    __syncthreads();
    ph2(W2c, b2c);
    __syncthreads();

    // ============ final gather + relu + global max pool ============
    {
        const char* Ub = (const char*)sm.U + lane * 4;
        float g = -FINF;
#pragma unroll 1
        for (int t = 0; t < 32; t++) {
            int n = base + t;
            const int4 ia = *(const int4*)&sm.idxb[n * 8];
            const int2 ib = *(const int2*)&sm.idxb[n * 8 + 4];
            float m =            *(const float*)(Ub + ia.x);
            m = fmaxf(m, *(const float*)(Ub + ia.y));
            m = fmaxf(m, *(const float*)(Ub + ia.z));
            m = fmaxf(m, *(const float*)(Ub + ia.w));
            m = fmaxf(m, *(const float*)(Ub + ib.x));
            m = fmaxf(m, *(const float*)(Ub + ib.y));
            g = fmaxf(g, fmaxf(m, 0.0f));     // relu then pool
        }
        sm.red[wid * C + lane] = g;
    }
    __syncthreads();

    if (wid == 0) {
        float gg = sm.red[lane];
#pragma unroll
        for (int w = 1; w < NWARP; w++)
            gg = fmaxf(gg, sm.red[w * C + lane]);
#pragma unroll
        for (int od = 0; od < 6; od++) {
            float p = Wr[od * C + lane] * gg;
#pragma unroll
            for (int off = 16; off > 0; off >>= 1)
                p += __shfl_xor_sync(0xffffffffu, p, off);
            if (lane == 0) out[b * 6 + od] = p + brr[od];
        }
    }
}

extern "C" void kernel_launch(void* const* d_in, const int* in_sizes, int n_in,
                              void* d_out, int out_size)
{
    const float* x   = (const float*)d_in[0];
    const float* pos = (const float*)d_in[1];
    // d_in[2] = batch (int64), implicit in layout
    const float* W1a = (const float*)d_in[3];
    const float* b1a = (const float*)d_in[4];
    const float* W2a = (const float*)d_in[5];
    const float* b2a = (const float*)d_in[6];
    const float* W1b = (const float*)d_in[7];
    const float* b1b = (const float*)d_in[8];
    const float* W2b = (const float*)d_in[9];
    const float* b2b = (const float*)d_in[10];
    const float* W1c = (const float*)d_in[11];
    const float* b1c = (const float*)d_in[12];
    const float* W2c = (const float*)d_in[13];
    const float* b2c = (const float*)d_in[14];
    const float* Wr  = (const float*)d_in[15];
    const float* brr = (const float*)d_in[16];
    float* out = (float*)d_out;

    knn_kernel<<<NGRAPH * 2, 256>>>(pos);

    const size_t smem = sizeof(SmemLayout);
    cudaFuncSetAttribute(gcn_layers_kernel,
                         cudaFuncAttributeMaxDynamicSharedMemorySize, (int)smem);
    gcn_layers_kernel<<<NGRAPH, 512, smem>>>(
        x, pos,
        W1a, b1a, W2a, b2a,
        W1b, b1b, W2b, b2b,
        W1c, b1c, W2c, b2c,
        Wr, brr, out);
}

// round 8
// speedup vs baseline: 1.1382x; 1.1382x over previous
#include <cuda_runtime.h>

#define NGRAPH 256
#define M      512
#define KNN    6
#define C      32
#define FINF   3.402823466e38f
#define ROWF   36            // padded U row length in floats (144B, 16B-aligned)
#define ROWB   144

typedef unsigned long long ull;

// KNN scratch, transposed [graph][k][node], pre-scaled to byte offsets (idx*ROWB)
__device__ int g_idxT[NGRAPH * KNN * M];

// ---- weights/biases in constant memory (uniform LDCU path, no L1 broadcast) ----
__constant__ ulonglong2 cW1a[32];     // 32x4  f32
__constant__ ulonglong2 cW2a[256];    // 32x32 f32
__constant__ ulonglong2 cW1b[256];
__constant__ ulonglong2 cW2b[256];
__constant__ ulonglong2 cW1c[256];
__constant__ ulonglong2 cW2c[256];
__constant__ float cb1a[32];
__constant__ float cb2a[32];
__constant__ float cb1b[32];
__constant__ float cb2b[32];
__constant__ float cb1c[32];
__constant__ float cb2c[32];
__constant__ float cWr[6 * 32];
__constant__ float cbr[6];

static __device__ __forceinline__ ull pk2(float lo, float hi) {
    ull d; asm("mov.b64 %0, {%1, %2};" : "=l"(d) : "f"(lo), "f"(hi)); return d;
}
static __device__ __forceinline__ float2 upk2(ull v) {
    float2 r; asm("mov.b64 {%0, %1}, %2;" : "=f"(r.x), "=f"(r.y) : "l"(v)); return r;
}
static __device__ __forceinline__ ull ffma2(ull a, ull b, ull c) {
    ull d; asm("fma.rn.f32x2 %0, %1, %2, %3;" : "=l"(d) : "l"(a), "l"(b), "l"(c)); return d;
}
static __device__ __forceinline__ float4 fmax4(float4 a, float4 b) {
    return make_float4(fmaxf(a.x, b.x), fmaxf(a.y, b.y),
                       fmaxf(a.z, b.z), fmaxf(a.w, b.w));
}

// 32x32 matvec, weights from constant, input packed p[16], relu, output packed op[16]
static __device__ __forceinline__ void matvec32_relu(const ulonglong2 (&W)[256],
                                                     const float (&B)[32],
                                                     const ull* __restrict__ p,
                                                     ull* __restrict__ op)
{
    float prev = 0.f;
#pragma unroll
    for (int o = 0; o < 32; o++) {
        ull a0 = 0, a1 = 0;
#pragma unroll
        for (int q = 0; q < 8; q++) {
            ulonglong2 w = W[o * 8 + q];
            a0 = ffma2(w.x, p[2 * q],     a0);
            a1 = ffma2(w.y, p[2 * q + 1], a1);
        }
        float2 e0 = upk2(a0), e1 = upk2(a1);
        float v = fmaxf((e0.x + e0.y) + (e1.x + e1.y) + B[o], 0.f);
        if (o & 1) op[o >> 1] = pk2(prev, v); else prev = v;
    }
}

// 32x32 matvec, no relu, streams result straight to the node's SMEM row (STS.64 pairs)
static __device__ __forceinline__ void matvec32_store(const ulonglong2 (&W)[256],
                                                      const float (&B)[32],
                                                      const ull* __restrict__ p,
                                                      float* __restrict__ Urow)
{
    float prev = 0.f;
#pragma unroll
    for (int o = 0; o < 32; o++) {
        ull a0 = 0, a1 = 0;
#pragma unroll
        for (int q = 0; q < 8; q++) {
            ulonglong2 w = W[o * 8 + q];
            a0 = ffma2(w.x, p[2 * q],     a0);
            a1 = ffma2(w.y, p[2 * q + 1], a1);
        }
        float2 e0 = upk2(a0), e1 = upk2(a1);
        float v = (e0.x + e0.y) + (e1.x + e1.y) + B[o];
        if (o & 1) *(ull*)(Urow + (o & ~1)) = pk2(prev, v); else prev = v;
    }
}

// gather-max over 6 neighbor rows + relu -> packed hp[16]; per-lane scattered LDS.128
static __device__ __forceinline__ void gather_relu(const char* __restrict__ Up,
                                                   const int* __restrict__ off,
                                                   ull* __restrict__ hp)
{
#pragma unroll
    for (int c4 = 0; c4 < 8; c4++) {
        int byo = c4 * 16;
        float4 m = *(const float4*)(Up + off[0] + byo);
        m = fmax4(m, *(const float4*)(Up + off[1] + byo));
        m = fmax4(m, *(const float4*)(Up + off[2] + byo));
        m = fmax4(m, *(const float4*)(Up + off[3] + byo));
        m = fmax4(m, *(const float4*)(Up + off[4] + byo));
        m = fmax4(m, *(const float4*)(Up + off[5] + byo));
        m.x = fmaxf(m.x, 0.f); m.y = fmaxf(m.y, 0.f);
        m.z = fmaxf(m.z, 0.f); m.w = fmaxf(m.w, 0.f);
        hp[2 * c4]     = pk2(m.x, m.y);
        hp[2 * c4 + 1] = pk2(m.z, m.w);
    }
}

__device__ __forceinline__ void kins(float (&bd)[KNN], int (&bi)[KNN],
                                     float xd, int xi)
{
#pragma unroll
    for (int k = 0; k < KNN; k++) {
        bool  p  = xd < bd[k];          // strict: stable (ties keep earlier j)
        float td = bd[k];
        int   ti = bi[k];
        bd[k] = p ? xd : bd[k];
        bi[k] = p ? xi : bi[k];
        xd    = p ? td : xd;
        xi    = p ? ti : xi;
    }
}

// ============================================================================
// Kernel 1: brute-force KNN. 1 block/graph, 256 threads, 2 nodes per thread.
// ============================================================================
__global__ void __launch_bounds__(256) knn_kernel(const float* __restrict__ pos)
{
    __shared__ float4 pos4s[M];
    const int b   = blockIdx.x;
    const int tid = threadIdx.x;

#pragma unroll
    for (int i = 0; i < 2; i++) {
        int nn = i * 256 + tid;
        const float* p = pos + ((size_t)b * M + nn) * 3;
        float px = p[0], py = p[1], pz = p[2];
        pos4s[nn] = make_float4(px, py, pz, px * px + py * py + pz * pz);
    }
    __syncthreads();

    float4 pA = pos4s[tid];
    float4 pB = pos4s[tid + 256];
    float bdA[KNN], bdB[KNN];
    int   biA[KNN], biB[KNN];
#pragma unroll
    for (int k = 0; k < KNN; k++) {
        bdA[k] = FINF; biA[k] = 0;
        bdB[k] = FINF; biB[k] = 0;
    }

#pragma unroll 2
    for (int j = 0; j < M; j++) {
        float4 pj = pos4s[j];
        float dA  = fmaf(pA.x, pj.x, fmaf(pA.y, pj.y, pA.z * pj.z));
        float dB  = fmaf(pB.x, pj.x, fmaf(pB.y, pj.y, pB.z * pj.z));
        float d2A = fmaf(-2.0f, dA, pA.w + pj.w);
        float d2B = fmaf(-2.0f, dB, pB.w + pj.w);
        if (d2A < bdA[KNN - 1]) kins(bdA, biA, d2A, j);
        if (d2B < bdB[KNN - 1]) kins(bdB, biB, d2B, j);
    }

    int* dst = g_idxT + (size_t)b * (KNN * M);
#pragma unroll
    for (int k = 0; k < KNN; k++) {
        dst[k * M + tid]       = biA[k] * ROWB;   // byte offsets
        dst[k * M + tid + 256] = biB[k] * ROWB;
    }
}

// ============================================================================
// Kernel 2: transposed fused layers. lane = node; weights via constant.
// ============================================================================
struct __align__(16) SmemL {
    float U0[M * ROWF];      // 73728 B
    float U1[M * ROWF];      // 73728 B
    float red[512];          //  2048 B
};                           // 149504 B total -> 1 CTA/SM

__global__ void __launch_bounds__(512, 1) gcn_layers_kernel(
    const float* __restrict__ x, const float* __restrict__ pos,
    float* __restrict__ out)
{
    extern __shared__ char smem_raw[];
    SmemL& sm = *reinterpret_cast<SmemL*>(smem_raw);

    const int b    = blockIdx.x;
    const int n    = threadIdx.x;          // own node
    const int lane = n & 31;
    const int wid  = n >> 5;

    int off[KNN];
    {
        const int* it = g_idxT + (size_t)b * (KNN * M) + n;
#pragma unroll
        for (int k = 0; k < KNN; k++) off[k] = it[k * M];
    }

    // ================= layer A: [x,px,py,pz] -> U0 =================
    {
        float xv = x[(size_t)b * M + n];
        const float* p = pos + ((size_t)b * M + n) * 3;
        ull in01 = pk2(xv, p[0]);
        ull in23 = pk2(p[1], p[2]);
        ull ap[16]; float prev = 0.f;
#pragma unroll
        for (int o = 0; o < 32; o++) {
            ulonglong2 w = cW1a[o];
            ull acc = ffma2(w.x, in01, ffma2(w.y, in23, 0ull));
            float2 e = upk2(acc);
            float v = fmaxf(e.x + e.y + cb1a[o], 0.f);
            if (o & 1) ap[o >> 1] = pk2(prev, v); else prev = v;
        }
        matvec32_store(cW2a, cb2a, ap, sm.U0 + n * ROWF);
    }
    __syncthreads();

    // ================= layer B: gather U0 -> U1 =================
    {
        ull hp[16], ap[16];
        gather_relu((const char*)sm.U0, off, hp);
        matvec32_relu(cW1b, cb1b, hp, ap);
        matvec32_store(cW2b, cb2b, ap, sm.U1 + n * ROWF);
    }
    __syncthreads();

    // ================= layer C: gather U1 -> U0 =================
    {
        ull hp[16], ap[16];
        gather_relu((const char*)sm.U1, off, hp);
        matvec32_relu(cW1c, cb1c, hp, ap);
        matvec32_store(cW2c, cb2c, ap, sm.U0 + n * ROWF);
    }
    __syncthreads();

    // ===== pool: self-loops => g[c] = relu(max_n u3[n][c]); no gather needed =====
    {
        int c = n & 31, s = n >> 5;            // 16 stripes x 32 channels
        const float* col = sm.U0 + c;
        float m = -FINF;
#pragma unroll
        for (int i = 0; i < 32; i++)
            m = fmaxf(m, col[(s * 32 + i) * ROWF]);   // conflict-free columns
        sm.red[s * 32 + c] = m;
    }
    __syncthreads();

    if (wid == 0) {
        float m = sm.red[lane];
#pragma unroll
        for (int s = 1; s < 16; s++) m = fmaxf(m, sm.red[s * 32 + lane]);
        float g = fmaxf(m, 0.f);
#pragma unroll
        for (int od = 0; od < 6; od++) {
            float pr = cWr[od * 32 + lane] * g;
#pragma unroll
            for (int o2 = 16; o2 > 0; o2 >>= 1)
                pr += __shfl_xor_sync(0xffffffffu, pr, o2);
            if (lane == 0) out[b * 6 + od] = pr + cbr[od];
        }
    }
}

extern "C" void kernel_launch(void* const* d_in, const int* in_sizes, int n_in,
                              void* d_out, int out_size)
{
    const float* x   = (const float*)d_in[0];
    const float* pos = (const float*)d_in[1];
    // d_in[2] = batch (int64), implicit in layout
    float* out = (float*)d_out;

    // raw-byte copies: consecutive float pairs ARE the f32x2 packed layout
    cudaMemcpyToSymbolAsync(cW1a, d_in[3],  512, 0, cudaMemcpyDeviceToDevice, 0);
    cudaMemcpyToSymbolAsync(cb1a, d_in[4],  128, 0, cudaMemcpyDeviceToDevice, 0);
    cudaMemcpyToSymbolAsync(cW2a, d_in[5], 4096, 0, cudaMemcpyDeviceToDevice, 0);
    cudaMemcpyToSymbolAsync(cb2a, d_in[6],  128, 0, cudaMemcpyDeviceToDevice, 0);
    cudaMemcpyToSymbolAsync(cW1b, d_in[7], 4096, 0, cudaMemcpyDeviceToDevice, 0);
    cudaMemcpyToSymbolAsync(cb1b, d_in[8],  128, 0, cudaMemcpyDeviceToDevice, 0);
    cudaMemcpyToSymbolAsync(cW2b, d_in[9], 4096, 0, cudaMemcpyDeviceToDevice, 0);
    cudaMemcpyToSymbolAsync(cb2b, d_in[10], 128, 0, cudaMemcpyDeviceToDevice, 0);
    cudaMemcpyToSymbolAsync(cW1c, d_in[11], 4096, 0, cudaMemcpyDeviceToDevice, 0);
    cudaMemcpyToSymbolAsync(cb1c, d_in[12], 128, 0, cudaMemcpyDeviceToDevice, 0);
    cudaMemcpyToSymbolAsync(cW2c, d_in[13], 4096, 0, cudaMemcpyDeviceToDevice, 0);
    cudaMemcpyToSymbolAsync(cb2c, d_in[14], 128, 0, cudaMemcpyDeviceToDevice, 0);
    cudaMemcpyToSymbolAsync(cWr,  d_in[15], 768, 0, cudaMemcpyDeviceToDevice, 0);
    cudaMemcpyToSymbolAsync(cbr,  d_in[16],  24, 0, cudaMemcpyDeviceToDevice, 0);

    knn_kernel<<<NGRAPH, 256>>>(pos);

    const size_t smem = sizeof(SmemL);
    cudaFuncSetAttribute(gcn_layers_kernel,
                         cudaFuncAttributeMaxDynamicSharedMemorySize, (int)smem);
    gcn_layers_kernel<<<NGRAPH, 512, smem>>>(x, pos, out);
}

// round 9
// speedup vs baseline: 1.4130x; 1.2415x over previous
#include <cuda_runtime.h>

#define NGRAPH 256
#define M      512
#define KNN    6
#define C      32
#define FINF   3.402823466e38f
#define ROWF   36            // padded U row (floats): 144B, 16B aligned, bank-rotating
#define ROWB   144
#define P1N    128           // KNN phase-1 sample size (exact tau upper bound)
#define CAP    128           // per-thread u16 candidate buffer capacity

typedef unsigned long long ull;

__device__ float g_A[NGRAPH * M * C];
__device__ int   g_idxT[NGRAPH * KNN * M];   // [graph][k][node], byte offsets (idx*ROWB)

__constant__ ulonglong2 cW1a[32];
__constant__ ulonglong2 cW2a[256];
__constant__ ulonglong2 cW1b[256];
__constant__ ulonglong2 cW2b[256];
__constant__ ulonglong2 cW1c[256];
__constant__ ulonglong2 cW2c[256];
__constant__ float cb1a[32];
__constant__ float cb2a[32];
__constant__ float cb1b[32];
__constant__ float cb2b[32];
__constant__ float cb1c[32];
__constant__ float cb2c[32];
__constant__ float cWr[6 * 32];
__constant__ float cbr[6];

static __device__ __forceinline__ ull pk2(float lo, float hi) {
    ull d; asm("mov.b64 %0, {%1, %2};" : "=l"(d) : "f"(lo), "f"(hi)); return d;
}
static __device__ __forceinline__ float2 upk2(ull v) {
    float2 r; asm("mov.b64 {%0, %1}, %2;" : "=f"(r.x), "=f"(r.y) : "l"(v)); return r;
}
static __device__ __forceinline__ ull ffma2(ull a, ull b, ull c) {
    ull d; asm("fma.rn.f32x2 %0, %1, %2, %3;" : "=l"(d) : "l"(a), "l"(b), "l"(c)); return d;
}
static __device__ __forceinline__ float4 fmax4(float4 a, float4 b) {
    return make_float4(fmaxf(a.x, b.x), fmaxf(a.y, b.y),
                       fmaxf(a.z, b.z), fmaxf(a.w, b.w));
}
static __device__ __forceinline__ void sts16_if(unsigned addr, unsigned short v, int pred) {
    asm volatile("{\n\t.reg .pred p;\n\tsetp.ne.s32 p, %2, 0;\n\t"
                 "@p st.shared.u16 [%0], %1;\n\t}"
                 :: "r"(addr), "h"(v), "r"(pred) : "memory");
}
static __device__ __forceinline__ float d2f(float4 a, float4 j) {
    float dot = fmaf(a.x, j.x, fmaf(a.y, j.y, a.z * j.z));
    return fmaf(-2.0f, dot, a.w + j.w);
}

__device__ __forceinline__ void kins(float (&bd)[KNN], int (&bi)[KNN],
                                     float xd, int xi)
{
#pragma unroll
    for (int k = 0; k < KNN; k++) {
        bool  p  = xd < bd[k];
        float td = bd[k];
        int   ti = bi[k];
        bd[k] = p ? xd : bd[k];
        bi[k] = p ? xi : bi[k];
        xd    = p ? td : xd;
        xi    = p ? ti : xi;
    }
}

// ============================================================================
// Kernel 1: 3-phase KNN. 1 block/graph, 256 threads, 2 nodes/thread.
// ============================================================================
struct __align__(16) SmemK {
    float4 pos4s[M];                  //  8 KB
    unsigned short buf[256 * CAP];    // 64 KB
};

__global__ void __launch_bounds__(256) knn_kernel(const float* __restrict__ pos)
{
    extern __shared__ char smem_raw[];
    SmemK& sk = *reinterpret_cast<SmemK*>(smem_raw);
    const int b = blockIdx.x;
    const int t = threadIdx.x;

#pragma unroll
    for (int i = 0; i < 2; i++) {
        int nn = i * 256 + t;
        const float* p = pos + ((size_t)b * M + nn) * 3;
        float px = p[0], py = p[1], pz = p[2];
        sk.pos4s[nn] = make_float4(px, py, pz, px * px + py * py + pz * pz);
    }
    __syncthreads();

    const float4 pA = sk.pos4s[t];
    const float4 pB = sk.pos4s[t + 256];

    // ---- phase 1: branchless value-only top-6 over first P1N candidates ----
    float vA[KNN], vB[KNN];
#pragma unroll
    for (int k = 0; k < KNN; k++) { vA[k] = FINF; vB[k] = FINF; }
#pragma unroll 2
    for (int j = 0; j < P1N; j++) {
        float4 pj = sk.pos4s[j];
        float a = d2f(pA, pj);
        float c = d2f(pB, pj);
#pragma unroll
        for (int k = 0; k < KNN; k++) {
            float lo = fminf(a, vA[k]); a = fmaxf(a, vA[k]); vA[k] = lo;
            float l2 = fminf(c, vB[k]); c = fmaxf(c, vB[k]); vB[k] = l2;
        }
    }
    const float tauA = vA[KNN - 1];
    const float tauB = vB[KNN - 1];

    // ---- phase 2: full scan, predicated append of candidates <= tau ----
    unsigned short* mybuf = sk.buf + t * CAP;
    unsigned bufaddr = (unsigned)__cvta_generic_to_shared(mybuf);
    int cnt = 0;
#pragma unroll 2
    for (int j = 0; j < M; j++) {
        float4 pj = sk.pos4s[j];
        float dA = d2f(pA, pj);
        float dB = d2f(pB, pj);
        int a  = dA <= tauA;
        int bb = dB <= tauB;
        int c0 = cnt < (CAP - 1) ? cnt : (CAP - 1);
        int c1 = (cnt + a) < (CAP - 1) ? (cnt + a) : (CAP - 1);
        sts16_if(bufaddr + 2u * (unsigned)c0, (unsigned short)j, a);
        sts16_if(bufaddr + 2u * (unsigned)c1, (unsigned short)(j | 512), bb);
        cnt += a + bb;
    }
    if (cnt > CAP) cnt = CAP;

    // ---- phase 3: exact stable top-6 over buffered candidates ----
    float bdA[KNN], bdB[KNN];
    int   biA[KNN], biB[KNN];
#pragma unroll
    for (int k = 0; k < KNN; k++) {
        bdA[k] = FINF; biA[k] = 0;
        bdB[k] = FINF; biB[k] = 0;
    }
    for (int i = 0; i < cnt; i++) {
        int e = mybuf[i];
        int j = e & 511;
        float4 pj = sk.pos4s[j];
        if (e & 512) {
            float d = d2f(pB, pj);
            if (d < bdB[KNN - 1]) kins(bdB, biB, d, j);
        } else {
            float d = d2f(pA, pj);
            if (d < bdA[KNN - 1]) kins(bdA, biA, d, j);
        }
    }

    int* dst = g_idxT + (size_t)b * (KNN * M);
#pragma unroll
    for (int k = 0; k < KNN; k++) {
        dst[k * M + t]       = biA[k] * ROWB;
        dst[k * M + t + 256] = biB[k] * ROWB;
    }
}

// ============================================================================
// Kernel 2: fused layers, 2 nodes/thread, 2 CTAs/SM.
// ============================================================================
struct __align__(16) SmemL {
    float U[M * ROWF];   // 73728 B
    float red[256];      //  1024 B
};

static __device__ __forceinline__ void gather_relu(const char* __restrict__ Up,
                                                   const int* __restrict__ off,
                                                   ull* __restrict__ hp)
{
#pragma unroll
    for (int c4 = 0; c4 < 8; c4++) {
        int byo = c4 * 16;
        float4 m = *(const float4*)(Up + off[0] + byo);
        m = fmax4(m, *(const float4*)(Up + off[1] + byo));
        m = fmax4(m, *(const float4*)(Up + off[2] + byo));
        m = fmax4(m, *(const float4*)(Up + off[3] + byo));
        m = fmax4(m, *(const float4*)(Up + off[4] + byo));
        m = fmax4(m, *(const float4*)(Up + off[5] + byo));
        m.x = fmaxf(m.x, 0.f); m.y = fmaxf(m.y, 0.f);
        m.z = fmaxf(m.z, 0.f); m.w = fmaxf(m.w, 0.f);
        hp[2 * c4]     = pk2(m.x, m.y);
        hp[2 * c4 + 1] = pk2(m.z, m.w);
    }
}

// dual-node 32x32 matvec rows with 4-wide store packing
#define MV_ROWS(W, BIAS, P0, P1, RELU, D0, D1)                                  \
    {                                                                           \
        ull s0lo = 0, s0hi = 0, s1lo = 0, s1hi = 0;                             \
        _Pragma("unroll")                                                       \
        for (int o = 0; o < 32; o++) {                                          \
            ull a0 = 0, a1 = 0, b0 = 0, b1 = 0;                                 \
            _Pragma("unroll")                                                   \
            for (int q = 0; q < 8; q++) {                                       \
                ulonglong2 w = (W)[o * 8 + q];                                  \
                a0 = ffma2(w.x, (P0)[2 * q],     a0);                           \
                a1 = ffma2(w.y, (P0)[2 * q + 1], a1);                           \
                b0 = ffma2(w.x, (P1)[2 * q],     b0);                           \
                b1 = ffma2(w.y, (P1)[2 * q + 1], b1);                           \
            }                                                                   \
            float2 e0 = upk2(a0), e1 = upk2(a1);                                \
            float2 f0 = upk2(b0), f1 = upk2(b1);                                \
            float v0 = (e0.x + e0.y) + (e1.x + e1.y) + (BIAS)[o];               \
            float v1 = (f0.x + f0.y) + (f1.x + f1.y) + (BIAS)[o];               \
            if (RELU) { v0 = fmaxf(v0, 0.f); v1 = fmaxf(v1, 0.f); }             \
            switch (o & 3) {                                                    \
              case 0: s0lo = pk2(v0, 0.f); s1lo = pk2(v1, 0.f); break;          \
              case 1: { float2 c0 = upk2(s0lo); s0lo = pk2(c0.x, v0);           \
                        float2 c1 = upk2(s1lo); s1lo = pk2(c1.x, v1); } break;  \
              case 2: s0hi = pk2(v0, 0.f); s1hi = pk2(v1, 0.f); break;          \
              default: {                                                        \
                float2 c0 = upk2(s0hi); s0hi = pk2(c0.x, v0);                   \
                float2 c1 = upk2(s1hi); s1hi = pk2(c1.x, v1);                   \
                *(ulonglong2*)((D0) + o - 3) = make_ulonglong2(s0lo, s0hi);     \
                *(ulonglong2*)((D1) + o - 3) = make_ulonglong2(s1lo, s1hi);     \
              } break;                                                          \
            }                                                                   \
        }                                                                       \
    }

__global__ void __launch_bounds__(256, 2) gcn_layers_kernel(
    const float* __restrict__ x, const float* __restrict__ pos,
    float* __restrict__ out)
{
    extern __shared__ char smem_raw[];
    SmemL& sm = *reinterpret_cast<SmemL*>(smem_raw);

    const int b    = blockIdx.x;
    const int t    = threadIdx.x;
    const int lane = t & 31;
    const int wid  = t >> 5;
    const int n0   = t;
    const int n1   = t + 256;

    float* __restrict__ Ag = g_A + (size_t)b * M * C;

    int off0[KNN], off1[KNN];
    {
        const int* it = g_idxT + (size_t)b * (KNN * M);
#pragma unroll
        for (int k = 0; k < KNN; k++) {
            off0[k] = it[k * M + n0];
            off1[k] = it[k * M + n1];
        }
    }

    // ============ layer A: all-register, straight to U ============
    {
        float x0 = x[(size_t)b * M + n0];
        float x1 = x[(size_t)b * M + n1];
        const float* p0 = pos + ((size_t)b * M + n0) * 3;
        const float* p1 = pos + ((size_t)b * M + n1) * 3;
        ull i0a = pk2(x0, p0[0]), i0b = pk2(p0[1], p0[2]);
        ull i1a = pk2(x1, p1[0]), i1b = pk2(p1[1], p1[2]);

        ull ap0[16], ap1[16];
        float pr0 = 0.f, pr1 = 0.f;
#pragma unroll
        for (int o = 0; o < 32; o++) {
            ulonglong2 w = cW1a[o];
            float2 e0 = upk2(ffma2(w.x, i0a, ffma2(w.y, i0b, 0ull)));
            float2 e1 = upk2(ffma2(w.x, i1a, ffma2(w.y, i1b, 0ull)));
            float v0 = fmaxf(e0.x + e0.y + cb1a[o], 0.f);
            float v1 = fmaxf(e1.x + e1.y + cb1a[o], 0.f);
            if (o & 1) { ap0[o >> 1] = pk2(pr0, v0); ap1[o >> 1] = pk2(pr1, v1); }
            else       { pr0 = v0; pr1 = v1; }
        }
        float* U0 = sm.U + n0 * ROWF;
        float* U1 = sm.U + n1 * ROWF;
        MV_ROWS(cW2a, cb2a, ap0, ap1, false, U0, U1);
    }
    __syncthreads();

    // ============ layers B, C ============
    {   // layer B ph1: gather + mv1 -> Ag
        ull hp0[16], hp1[16];
        gather_relu((const char*)sm.U, off0, hp0);
        gather_relu((const char*)sm.U, off1, hp1);
        float* A0 = Ag + n0 * C;
        float* A1 = Ag + n1 * C;
        MV_ROWS(cW1b, cb1b, hp0, hp1, true, A0, A1);
    }
    __syncthreads();
    {   // layer B ph2: Ag -> U
        ull ap0[16], ap1[16];
        const ulonglong2* r0 = (const ulonglong2*)(Ag + n0 * C);
        const ulonglong2* r1 = (const ulonglong2*)(Ag + n1 * C);
#pragma unroll
        for (int q = 0; q < 8; q++) {
            ulonglong2 v0 = r0[q]; ap0[2 * q] = v0.x; ap0[2 * q + 1] = v0.y;
            ulonglong2 v1 = r1[q]; ap1[2 * q] = v1.x; ap1[2 * q + 1] = v1.y;
        }
        float* U0 = sm.U + n0 * ROWF;
        float* U1 = sm.U + n1 * ROWF;
        MV_ROWS(cW2b, cb2b, ap0, ap1, false, U0, U1);
    }
    __syncthreads();
    {   // layer C ph1
        ull hp0[16], hp1[16];
        gather_relu((const char*)sm.U, off0, hp0);
        gather_relu((const char*)sm.U, off1, hp1);
        float* A0 = Ag + n0 * C;
        float* A1 = Ag + n1 * C;
        MV_ROWS(cW1c, cb1c, hp0, hp1, true, A0, A1);
    }
    __syncthreads();
    {   // layer C ph2
        ull ap0[16], ap1[16];
        const ulonglong2* r0 = (const ulonglong2*)(Ag + n0 * C);
        const ulonglong2* r1 = (const ulonglong2*)(Ag + n1 * C);
#pragma unroll
        for (int q = 0; q < 8; q++) {
            ulonglong2 v0 = r0[q]; ap0[2 * q] = v0.x; ap0[2 * q + 1] = v0.y;
            ulonglong2 v1 = r1[q]; ap1[2 * q] = v1.x; ap1[2 * q + 1] = v1.y;
        }
        float* U0 = sm.U + n0 * ROWF;
        float* U1 = sm.U + n1 * ROWF;
        MV_ROWS(cW2c, cb2c, ap0, ap1, false, U0, U1);
    }
    __syncthreads();

    // ===== pool: self-loops => g[c] = relu(max_n u3[n][c]) =====
    {
        int c = t & 31, s = t >> 5;        // 8 stripes x 64 rows
        const float* col = sm.U + c;
        float m = -FINF;
#pragma unroll 4
        for (int i = 0; i < 64; i++)
            m = fmaxf(m, col[(s * 64 + i) * ROWF]);
        sm.red[s * 32 + c] = m;
    }
    __syncthreads();

    if (wid == 0) {
        float m = sm.red[lane];
#pragma unroll
        for (int s = 1; s < 8; s++) m = fmaxf(m, sm.red[s * 32 + lane]);
        float g = fmaxf(m, 0.f);
#pragma unroll
        for (int od = 0; od < 6; od++) {
            float pr = cWr[od * 32 + lane] * g;
#pragma unroll
            for (int o2 = 16; o2 > 0; o2 >>= 1)
                pr += __shfl_xor_sync(0xffffffffu, pr, o2);
            if (lane == 0) out[b * 6 + od] = pr + cbr[od];
        }
    }
}

extern "C" void kernel_launch(void* const* d_in, const int* in_sizes, int n_in,
                              void* d_out, int out_size)
{
    const float* x   = (const float*)d_in[0];
    const float* pos = (const float*)d_in[1];
    float* out = (float*)d_out;

    cudaMemcpyToSymbolAsync(cW1a, d_in[3],  512, 0, cudaMemcpyDeviceToDevice, 0);
    cudaMemcpyToSymbolAsync(cb1a, d_in[4],  128, 0, cudaMemcpyDeviceToDevice, 0);
    cudaMemcpyToSymbolAsync(cW2a, d_in[5], 4096, 0, cudaMemcpyDeviceToDevice, 0);
    cudaMemcpyToSymbolAsync(cb2a, d_in[6],  128, 0, cudaMemcpyDeviceToDevice, 0);
    cudaMemcpyToSymbolAsync(cW1b, d_in[7], 4096, 0, cudaMemcpyDeviceToDevice, 0);
    cudaMemcpyToSymbolAsync(cb1b, d_in[8],  128, 0, cudaMemcpyDeviceToDevice, 0);
    cudaMemcpyToSymbolAsync(cW2b, d_in[9], 4096, 0, cudaMemcpyDeviceToDevice, 0);
    cudaMemcpyToSymbolAsync(cb2b, d_in[10], 128, 0, cudaMemcpyDeviceToDevice, 0);
    cudaMemcpyToSymbolAsync(cW1c, d_in[11], 4096, 0, cudaMemcpyDeviceToDevice, 0);
    cudaMemcpyToSymbolAsync(cb1c, d_in[12], 128, 0, cudaMemcpyDeviceToDevice, 0);
    cudaMemcpyToSymbolAsync(cW2c, d_in[13], 4096, 0, cudaMemcpyDeviceToDevice, 0);
    cudaMemcpyToSymbolAsync(cb2c, d_in[14], 128, 0, cudaMemcpyDeviceToDevice, 0);
    cudaMemcpyToSymbolAsync(cWr,  d_in[15], 768, 0, cudaMemcpyDeviceToDevice, 0);
    cudaMemcpyToSymbolAsync(cbr,  d_in[16],  24, 0, cudaMemcpyDeviceToDevice, 0);

    cudaFuncSetAttribute(knn_kernel,
                         cudaFuncAttributeMaxDynamicSharedMemorySize, (int)sizeof(SmemK));
    knn_kernel<<<NGRAPH, 256, sizeof(SmemK)>>>(pos);

    cudaFuncSetAttribute(gcn_layers_kernel,
                         cudaFuncAttributeMaxDynamicSharedMemorySize, (int)sizeof(SmemL));
    gcn_layers_kernel<<<NGRAPH, 256, sizeof(SmemL)>>>(x, pos, out);
}

// round 10
// speedup vs baseline: 1.8703x; 1.3236x over previous
#include <cuda_runtime.h>

#define NGRAPH 256
#define M      512
#define KNN    6
#define C      32
#define FINF   3.402823466e38f
#define ROWF   36            // padded U row (floats): 144B, 16B aligned
#define ROWB   144
#define P1N    128           // KNN phase-1 sample size (exact tau upper bound)
#define CAP    96            // per-thread u16 candidate buffer capacity

typedef unsigned long long ull;

__device__ float g_A[NGRAPH * M * C];
__device__ int   g_idxT[NGRAPH * KNN * M];   // [graph][k][node], byte offsets (idx*ROWB)
__device__ float g_pack[5638];

// single consolidated constant block (16B aligned); offsets in floats
__constant__ __align__(16) float cALL[5640];
#define W1A ((const ulonglong2*)(cALL + 0))      // 32x4
#define B1A (cALL + 128)
#define W2A ((const ulonglong2*)(cALL + 160))    // 32x32
#define B2A (cALL + 1184)
#define W1B ((const ulonglong2*)(cALL + 1216))
#define B1B (cALL + 2240)
#define W2B ((const ulonglong2*)(cALL + 2272))
#define B2B (cALL + 3296)
#define W1C ((const ulonglong2*)(cALL + 3328))
#define B1C (cALL + 4352)
#define W2C ((const ulonglong2*)(cALL + 4384))
#define B2C (cALL + 5408)
#define WR  (cALL + 5440)
#define BR  (cALL + 5632)

static __device__ __forceinline__ ull pk2(float lo, float hi) {
    ull d; asm("mov.b64 %0, {%1, %2};" : "=l"(d) : "f"(lo), "f"(hi)); return d;
}
static __device__ __forceinline__ float2 upk2(ull v) {
    float2 r; asm("mov.b64 {%0, %1}, %2;" : "=f"(r.x), "=f"(r.y) : "l"(v)); return r;
}
static __device__ __forceinline__ ull ffma2(ull a, ull b, ull c) {
    ull d; asm("fma.rn.f32x2 %0, %1, %2, %3;" : "=l"(d) : "l"(a), "l"(b), "l"(c)); return d;
}
static __device__ __forceinline__ float4 fmax4(float4 a, float4 b) {
    return make_float4(fmaxf(a.x, b.x), fmaxf(a.y, b.y),
                       fmaxf(a.z, b.z), fmaxf(a.w, b.w));
}
// predicated 16-bit shared store; no memory clobber (one barrier after the loop)
static __device__ __forceinline__ void sts16_if(unsigned addr, unsigned short v, int pred) {
    asm volatile("{\n\t.reg .pred p;\n\tsetp.ne.s32 p, %2, 0;\n\t"
                 "@p st.shared.u16 [%0], %1;\n\t}"
                 :: "r"(addr), "h"(v), "r"(pred));
}
static __device__ __forceinline__ float d2f(float4 a, float4 j) {
    float dot = fmaf(a.x, j.x, fmaf(a.y, j.y, a.z * j.z));
    return fmaf(-2.0f, dot, a.w + j.w);       // exact reference formula
}

__device__ __forceinline__ void kins(float (&bd)[KNN], int (&bi)[KNN],
                                     float xd, int xi)
{
#pragma unroll
    for (int k = 0; k < KNN; k++) {
        bool  p  = xd < bd[k];                // strict: stable (ties keep earlier j)
        float td = bd[k];
        int   ti = bi[k];
        bd[k] = p ? xd : bd[k];
        bi[k] = p ? xi : bi[k];
        xd    = p ? td : xd;
        xi    = p ? ti : xi;
    }
}

// ============================================================================
// Kernel 0: pack all weights into one device buffer (then 1 symbol memcpy)
// ============================================================================
__global__ void pack_weights(
    const float* W1a, const float* b1a, const float* W2a, const float* b2a,
    const float* W1b, const float* b1b, const float* W2b, const float* b2b,
    const float* W1c, const float* b1c, const float* W2c, const float* b2c,
    const float* Wr,  const float* br)
{
    const int t = threadIdx.x;   // 256 threads
    for (int i = t; i < 128;  i += 256) g_pack[0    + i] = W1a[i];
    for (int i = t; i < 32;   i += 256) g_pack[128  + i] = b1a[i];
    for (int i = t; i < 1024; i += 256) g_pack[160  + i] = W2a[i];
    for (int i = t; i < 32;   i += 256) g_pack[1184 + i] = b2a[i];
    for (int i = t; i < 1024; i += 256) g_pack[1216 + i] = W1b[i];
    for (int i = t; i < 32;   i += 256) g_pack[2240 + i] = b1b[i];
    for (int i = t; i < 1024; i += 256) g_pack[2272 + i] = W2b[i];
    for (int i = t; i < 32;   i += 256) g_pack[3296 + i] = b2b[i];
    for (int i = t; i < 1024; i += 256) g_pack[3328 + i] = W1c[i];
    for (int i = t; i < 32;   i += 256) g_pack[4352 + i] = b1c[i];
    for (int i = t; i < 1024; i += 256) g_pack[4384 + i] = W2c[i];
    for (int i = t; i < 32;   i += 256) g_pack[5408 + i] = b2c[i];
    for (int i = t; i < 192;  i += 256) g_pack[5440 + i] = Wr[i];
    for (int i = t; i < 6;    i += 256) g_pack[5632 + i] = br[i];
}

// ============================================================================
// Kernel 1: 3-phase KNN. 2 blocks/graph, 256 threads, 1 node/thread.
// ============================================================================
struct __align__(16) SmemK {
    float4 pos4s[M];                  //  8 KB
    unsigned short buf[256 * CAP];    // 48 KB
};

__global__ void __launch_bounds__(256, 4) knn_kernel(const float* __restrict__ pos)
{
    extern __shared__ char smem_raw[];
    SmemK& sk = *reinterpret_cast<SmemK*>(smem_raw);
    const int b    = blockIdx.x >> 1;
    const int half = blockIdx.x & 1;
    const int t    = threadIdx.x;

#pragma unroll
    for (int i = 0; i < 2; i++) {
        int nn = i * 256 + t;
        const float* p = pos + ((size_t)b * M + nn) * 3;
        float px = p[0], py = p[1], pz = p[2];
        sk.pos4s[nn] = make_float4(px, py, pz, px * px + py * py + pz * pz);
    }
    __syncthreads();

    const int n = half * 256 + t;
    const float4 pn = sk.pos4s[n];

    // ---- phase 1: branchless value-only top-6 over first P1N (exact d2) ----
    float v[KNN];
#pragma unroll
    for (int k = 0; k < KNN; k++) v[k] = FINF;
#pragma unroll 2
    for (int j = 0; j < P1N; j++) {
        float a = d2f(pn, sk.pos4s[j]);
#pragma unroll
        for (int k = 0; k < KNN; k++) {
            float lo = fminf(a, v[k]); a = fmaxf(a, v[k]); v[k] = lo;
        }
    }
    // filter threshold in the cheap metric e_j = jw - 2*dot  (margin covers rounding)
    const float taup = (v[KNN - 1] - pn.w) + 1e-4f;

    // ---- phase 2: full scan, predicated append of candidates ----
    unsigned short* mybuf = sk.buf + t * CAP;
    unsigned bufaddr = (unsigned)__cvta_generic_to_shared(mybuf);
    int cnt = 0;
#pragma unroll 1
    for (int j0 = 0; j0 < M; j0 += 4) {
        float e[4];
#pragma unroll
        for (int u = 0; u < 4; u++) {
            float4 pj = sk.pos4s[j0 + u];
            float dot = fmaf(pn.x, pj.x, fmaf(pn.y, pj.y, pn.z * pj.z));
            e[u] = fmaf(-2.0f, dot, pj.w);
        }
        int basec = cnt < (CAP - 4) ? cnt : (CAP - 4);
#pragma unroll
        for (int u = 0; u < 4; u++) {
            int p = e[u] <= taup;
            sts16_if(bufaddr + 2u * (unsigned)basec, (unsigned short)(j0 + u), p);
            basec += p;
            cnt   += p;
        }
    }
    asm volatile("" ::: "memory");   // order buffered stores before phase-3 reads

    // ---- phase 3: exact stable top-6 ----
    float bd[KNN];
    int   bi[KNN];
#pragma unroll
    for (int k = 0; k < KNN; k++) { bd[k] = FINF; bi[k] = 0; }

    if (cnt <= CAP) {
        for (int i = 0; i < cnt; i++) {
            int j = mybuf[i];
            float d = d2f(pn, sk.pos4s[j]);
            if (d < bd[KNN - 1]) kins(bd, bi, d, j);
        }
    } else {
        // astronomically rare exact fallback: full stable scan
        for (int j = 0; j < M; j++) {
            float d = d2f(pn, sk.pos4s[j]);
            if (d < bd[KNN - 1]) kins(bd, bi, d, j);
        }
    }

    int* dst = g_idxT + (size_t)b * (KNN * M);
#pragma unroll
    for (int k = 0; k < KNN; k++)
        dst[k * M + n] = bi[k] * ROWB;
}

// ============================================================================
// Kernel 2: fused layers, 2 nodes/thread, 2 CTAs/SM. (unchanged structure)
// ============================================================================
struct __align__(16) SmemL {
    float U[M * ROWF];   // 73728 B
    float red[256];      //  1024 B
};

static __device__ __forceinline__ void gather_relu(const char* __restrict__ Up,
                                                   const int* __restrict__ off,
                                                   ull* __restrict__ hp)
{
#pragma unroll
    for (int c4 = 0; c4 < 8; c4++) {
        int byo = c4 * 16;
        float4 m = *(const float4*)(Up + off[0] + byo);
        m = fmax4(m, *(const float4*)(Up + off[1] + byo));
        m = fmax4(m, *(const float4*)(Up + off[2] + byo));
        m = fmax4(m, *(const float4*)(Up + off[3] + byo));
        m = fmax4(m, *(const float4*)(Up + off[4] + byo));
        m = fmax4(m, *(const float4*)(Up + off[5] + byo));
        m.x = fmaxf(m.x, 0.f); m.y = fmaxf(m.y, 0.f);
        m.z = fmaxf(m.z, 0.f); m.w = fmaxf(m.w, 0.f);
        hp[2 * c4]     = pk2(m.x, m.y);
        hp[2 * c4 + 1] = pk2(m.z, m.w);
    }
}

#define MV_ROWS(W, BIAS, P0, P1, RELU, D0, D1)                                  \
    {                                                                           \
        ull s0lo = 0, s0hi = 0, s1lo = 0, s1hi = 0;                             \
        _Pragma("unroll")                                                       \
        for (int o = 0; o < 32; o++) {                                          \
            ull a0 = 0, a1 = 0, b0 = 0, b1 = 0;                                 \
            _Pragma("unroll")                                                   \
            for (int q = 0; q < 8; q++) {                                       \
                ulonglong2 w = (W)[o * 8 + q];                                  \
                a0 = ffma2(w.x, (P0)[2 * q],     a0);                           \
                a1 = ffma2(w.y, (P0)[2 * q + 1], a1);                           \
                b0 = ffma2(w.x, (P1)[2 * q],     b0);                           \
                b1 = ffma2(w.y, (P1)[2 * q + 1], b1);                           \
            }                                                                   \
            float2 e0 = upk2(a0), e1 = upk2(a1);                                \
            float2 f0 = upk2(b0), f1 = upk2(b1);                                \
            float v0 = (e0.x + e0.y) + (e1.x + e1.y) + (BIAS)[o];               \
            float v1 = (f0.x + f0.y) + (f1.x + f1.y) + (BIAS)[o];               \
            if (RELU) { v0 = fmaxf(v0, 0.f); v1 = fmaxf(v1, 0.f); }             \
            switch (o & 3) {                                                    \
              case 0: s0lo = pk2(v0, 0.f); s1lo = pk2(v1, 0.f); break;          \
              case 1: { float2 c0 = upk2(s0lo); s0lo = pk2(c0.x, v0);           \
                        float2 c1 = upk2(s1lo); s1lo = pk2(c1.x, v1); } break;  \
              case 2: s0hi = pk2(v0, 0.f); s1hi = pk2(v1, 0.f); break;          \
              default: {                                                        \
                float2 c0 = upk2(s0hi); s0hi = pk2(c0.x, v0);                   \
                float2 c1 = upk2(s1hi); s1hi = pk2(c1.x, v1);                   \
                *(ulonglong2*)((D0) + o - 3) = make_ulonglong2(s0lo, s0hi);     \
                *(ulonglong2*)((D1) + o - 3) = make_ulonglong2(s1lo, s1hi);     \
              } break;                                                          \
            }                                                                   \
        }                                                                       \
    }

__global__ void __launch_bounds__(256, 2) gcn_layers_kernel(
    const float* __restrict__ x, const float* __restrict__ pos,
    float* __restrict__ out)
{
    extern __shared__ char smem_raw[];
    SmemL& sm = *reinterpret_cast<SmemL*>(smem_raw);

    const int b    = blockIdx.x;
    const int t    = threadIdx.x;
    const int lane = t & 31;
    const int wid  = t >> 5;
    const int n0   = t;
    const int n1   = t + 256;

    float* __restrict__ Ag = g_A + (size_t)b * M * C;

    int off0[KNN], off1[KNN];
    {
        const int* it = g_idxT + (size_t)b * (KNN * M);
#pragma unroll
        for (int k = 0; k < KNN; k++) {
            off0[k] = it[k * M + n0];
            off1[k] = it[k * M + n1];
        }
    }

    // ============ layer A: all-register, straight to U ============
    {
        float x0 = x[(size_t)b * M + n0];
        float x1 = x[(size_t)b * M + n1];
        const float* p0 = pos + ((size_t)b * M + n0) * 3;
        const float* p1 = pos + ((size_t)b * M + n1) * 3;
        ull i0a = pk2(x0, p0[0]), i0b = pk2(p0[1], p0[2]);
        ull i1a = pk2(x1, p1[0]), i1b = pk2(p1[1], p1[2]);

        ull ap0[16], ap1[16];
        float pr0 = 0.f, pr1 = 0.f;
#pragma unroll
        for (int o = 0; o < 32; o++) {
            ulonglong2 w = W1A[o];
            float2 e0 = upk2(ffma2(w.x, i0a, ffma2(w.y, i0b, 0ull)));
            float2 e1 = upk2(ffma2(w.x, i1a, ffma2(w.y, i1b, 0ull)));
            float v0 = fmaxf(e0.x + e0.y + B1A[o], 0.f);
            float v1 = fmaxf(e1.x + e1.y + B1A[o], 0.f);
            if (o & 1) { ap0[o >> 1] = pk2(pr0, v0); ap1[o >> 1] = pk2(pr1, v1); }
            else       { pr0 = v0; pr1 = v1; }
        }
        float* U0 = sm.U + n0 * ROWF;
        float* U1 = sm.U + n1 * ROWF;
        MV_ROWS(W2A, B2A, ap0, ap1, false, U0, U1);
    }
    __syncthreads();

    {   // layer B ph1: gather + mv1 -> Ag
        ull hp0[16], hp1[16];
        gather_relu((const char*)sm.U, off0, hp0);
        gather_relu((const char*)sm.U, off1, hp1);
        float* A0 = Ag + n0 * C;
        float* A1 = Ag + n1 * C;
        MV_ROWS(W1B, B1B, hp0, hp1, true, A0, A1);
    }
    __syncthreads();
    {   // layer B ph2: Ag -> U
        ull ap0[16], ap1[16];
        const ulonglong2* r0 = (const ulonglong2*)(Ag + n0 * C);
        const ulonglong2* r1 = (const ulonglong2*)(Ag + n1 * C);
#pragma unroll
        for (int q = 0; q < 8; q++) {
            ulonglong2 v0 = r0[q]; ap0[2 * q] = v0.x; ap0[2 * q + 1] = v0.y;
            ulonglong2 v1 = r1[q]; ap1[2 * q] = v1.x; ap1[2 * q + 1] = v1.y;
        }
        float* U0 = sm.U + n0 * ROWF;
        float* U1 = sm.U + n1 * ROWF;
        MV_ROWS(W2B, B2B, ap0, ap1, false, U0, U1);
    }
    __syncthreads();
    {   // layer C ph1
        ull hp0[16], hp1[16];
        gather_relu((const char*)sm.U, off0, hp0);
        gather_relu((const char*)sm.U, off1, hp1);
        float* A0 = Ag + n0 * C;
        float* A1 = Ag + n1 * C;
        MV_ROWS(W1C, B1C, hp0, hp1, true, A0, A1);
    }
    __syncthreads();
    {   // layer C ph2
        ull ap0[16], ap1[16];
        const ulonglong2* r0 = (const ulonglong2*)(Ag + n0 * C);
        const ulonglong2* r1 = (const ulonglong2*)(Ag + n1 * C);
#pragma unroll
        for (int q = 0; q < 8; q++) {
            ulonglong2 v0 = r0[q]; ap0[2 * q] = v0.x; ap0[2 * q + 1] = v0.y;
            ulonglong2 v1 = r1[q]; ap1[2 * q] = v1.x; ap1[2 * q + 1] = v1.y;
        }
        float* U0 = sm.U + n0 * ROWF;
        float* U1 = sm.U + n1 * ROWF;
        MV_ROWS(W2C, B2C, ap0, ap1, false, U0, U1);
    }
    __syncthreads();

    // ===== pool: self-loops => g[c] = relu(max_n u3[n][c]) =====
    {
        int c = t & 31, s = t >> 5;
        const float* col = sm.U + c;
        float m = -FINF;
#pragma unroll 4
        for (int i = 0; i < 64; i++)
            m = fmaxf(m, col[(s * 64 + i) * ROWF]);
        sm.red[s * 32 + c] = m;
    }
    __syncthreads();

    if (wid == 0) {
        float m = sm.red[lane];
#pragma unroll
        for (int s = 1; s < 8; s++) m = fmaxf(m, sm.red[s * 32 + lane]);
        float g = fmaxf(m, 0.f);
#pragma unroll
        for (int od = 0; od < 6; od++) {
            float pr = WR[od * 32 + lane] * g;
#pragma unroll
            for (int o2 = 16; o2 > 0; o2 >>= 1)
                pr += __shfl_xor_sync(0xffffffffu, pr, o2);
            if (lane == 0) out[b * 6 + od] = pr + BR[od];
        }
    }
}

extern "C" void kernel_launch(void* const* d_in, const int* in_sizes, int n_in,
                              void* d_out, int out_size)
{
    const float* x   = (const float*)d_in[0];
    const float* pos = (const float*)d_in[1];
    float* out = (float*)d_out;

    pack_weights<<<1, 256>>>(
        (const float*)d_in[3],  (const float*)d_in[4],
        (const float*)d_in[5],  (const float*)d_in[6],
        (const float*)d_in[7],  (const float*)d_in[8],
        (const float*)d_in[9],  (const float*)d_in[10],
        (const float*)d_in[11], (const float*)d_in[12],
        (const float*)d_in[13], (const float*)d_in[14],
        (const float*)d_in[15], (const float*)d_in[16]);

    void* packp = nullptr;
    cudaGetSymbolAddress(&packp, g_pack);
    cudaMemcpyToSymbolAsync(cALL, packp, 5638 * sizeof(float), 0,
                            cudaMemcpyDeviceToDevice, 0);

    cudaFuncSetAttribute(knn_kernel,
                         cudaFuncAttributeMaxDynamicSharedMemorySize, (int)sizeof(SmemK));
    knn_kernel<<<NGRAPH * 2, 256, sizeof(SmemK)>>>(pos);

    cudaFuncSetAttribute(gcn_layers_kernel,
                         cudaFuncAttributeMaxDynamicSharedMemorySize, (int)sizeof(SmemL));
    gcn_layers_kernel<<<NGRAPH, 256, sizeof(SmemL)>>>(x, pos, out);
}